// round 1
// baseline (speedup 1.0000x reference)
#include <cuda_runtime.h>
#include <math.h>

#define HID   512
#define G     8      // points per block
#define T     512    // threads per block
#define KT    32     // K-tile rows staged in shared
#define N_INT_MAX 20000
#define N_BND_MAX 800
#define ALPHA 0.01f

__device__ float g_lap[N_INT_MAX];
__device__ float g_u[N_BND_MAX];

typedef unsigned long long u64;

__device__ __forceinline__ u64 pack2(float lo, float hi) {
    u64 r; asm("mov.b64 %0, {%1,%2};" : "=l"(r) : "f"(lo), "f"(hi)); return r;
}
__device__ __forceinline__ void unpack2(u64 v, float& lo, float& hi) {
    asm("mov.b64 {%0,%1}, %2;" : "=f"(lo), "=f"(hi) : "l"(v));
}
// packed dual fp32 FMA: d = a*b + d  (sm_100+ f32x2 pipe, 2x fp32 throughput)
__device__ __forceinline__ void fma2(u64& d, u64 a, u64 b) {
    asm("fma.rn.f32x2 %0, %1, %2, %0;" : "+l"(d) : "l"(a), "l"(b));
}

// tanh forward-mode 2nd-order jet: value, d/dx, d/dy, d2/dx2, d2/dy2
__device__ __forceinline__ void tanh_jet(float zv, float zx, float zy, float zxx, float zyy,
                                         float& av, float& ax, float& ay, float& axx, float& ayy) {
    float t = tanhf(zv);
    float s = 1.0f - t * t;
    av = t;
    ax = s * zx;
    ay = s * zy;
    axx = fmaf(-2.0f * t * zx, ax, s * zxx);
    ayy = fmaf(-2.0f * t * zy, ay, s * zyy);
}

__global__ void __launch_bounds__(T, 1)
pinn_main(const float* __restrict__ xi, const float* __restrict__ xb,
          const float* __restrict__ W0, const float* __restrict__ b0,
          const float* __restrict__ W1, const float* __restrict__ b1,
          const float* __restrict__ W2, const float* __restrict__ b2,
          const float* __restrict__ W3, const float* __restrict__ b3,
          int n_int, int n_bnd)
{
    extern __shared__ float smem[];
    float*  s_w = smem;                                  // KT*HID floats (64KB)
    float2* s_d = (float2*)(smem + KT * HID);            // G*HID float2 (32KB)
    float2* s_h = s_d + G * HID;                         // G*HID float2 (32KB)
    float*  s_v = (float*)(s_h + G * HID);               // G*HID floats (16KB)

    const int tid = threadIdx.x;
    const int p   = tid >> 6;      // point within block (0..7)
    const int sub = tid & 63;      // thread within point (0..63)
    const long gp = (long)blockIdx.x * G + p;
    const int n_total = n_int + n_bnd;
    const bool active = gp < n_total;

    float x = 0.0f, y = 0.0f;
    if (active) {
        const float* src = (gp < n_int) ? (xi + 2 * gp) : (xb + 2 * (gp - n_int));
        x = src[0]; y = src[1];
    }

    // ---------------- layer 0: (x,y) -> 512, tanh ----------------
    // jet at input: v=(x,y), dx=(1,0), dy=(0,1), second derivs 0
    #pragma unroll
    for (int i = 0; i < 4; i++) {
        int q = sub + 64 * i;          // channel-pair index
        #pragma unroll
        for (int h2 = 0; h2 < 2; h2++) {
            int j = 2 * q + h2;
            float w0x = W0[j];
            float w0y = W0[HID + j];
            float zv = fmaf(x, w0x, fmaf(y, w0y, b0[j]));
            float av, ax, ay, axx, ayy;
            tanh_jet(zv, w0x, w0y, 0.0f, 0.0f, av, ax, ay, axx, ayy);
            s_v[p * HID + j] = av;
            s_d[p * HID + j] = make_float2(ax, ay);
            s_h[p * HID + j] = make_float2(axx, ayy);
        }
    }
    __syncthreads();

    // ---------------- hidden layers 1,2: 512 -> 512, tanh ----------------
    const float* Wlist[2] = { W1, W2 };
    const float* blist[2] = { b1, b2 };
    for (int L = 0; L < 2; L++) {
        const float* __restrict__ W = Wlist[L];
        const float* __restrict__ b = blist[L];

        u64 accv[4], accx[4], accy[4], accxx[4], accyy[4];
        #pragma unroll
        for (int i = 0; i < 4; i++) {
            accv[i] = 0ull; accx[i] = 0ull; accy[i] = 0ull; accxx[i] = 0ull; accyy[i] = 0ull;
        }

        for (int kt = 0; kt < HID; kt += KT) {
            // cooperative load of W rows [kt, kt+KT) into shared (float4, coalesced)
            const float4* Wg  = (const float4*)(W + kt * HID);
            float4*       swg = (float4*)s_w;
            #pragma unroll
            for (int u = 0; u < (KT * HID / 4) / T; u++) {
                swg[tid + u * T] = Wg[tid + u * T];
            }
            __syncthreads();

            #pragma unroll 4
            for (int k = 0; k < KT; k++) {
                int kk = kt + k;
                float  av = s_v[p * HID + kk];
                float2 ad = s_d[p * HID + kk];
                float2 ah = s_h[p * HID + kk];
                u64 AV  = pack2(av,   av);
                u64 AX  = pack2(ad.x, ad.x);
                u64 AY  = pack2(ad.y, ad.y);
                u64 AXX = pack2(ah.x, ah.x);
                u64 AYY = pack2(ah.y, ah.y);
                const float* wrow = s_w + k * HID;
                #pragma unroll
                for (int i = 0; i < 4; i++) {
                    u64 wp = *(const u64*)(wrow + 2 * (sub + 64 * i));
                    fma2(accv[i],  AV,  wp);
                    fma2(accx[i],  AX,  wp);
                    fma2(accy[i],  AY,  wp);
                    fma2(accxx[i], AXX, wp);
                    fma2(accyy[i], AYY, wp);
                }
            }
            __syncthreads();
        }

        // tanh + writeback (safe: barrier above means all reads of s_* done)
        #pragma unroll
        for (int i = 0; i < 4; i++) {
            float v0, v1, dx0, dx1, dy0, dy1, hx0, hx1, hy0, hy1;
            unpack2(accv[i],  v0,  v1);
            unpack2(accx[i],  dx0, dx1);
            unpack2(accy[i],  dy0, dy1);
            unpack2(accxx[i], hx0, hx1);
            unpack2(accyy[i], hy0, hy1);
            int j0 = 2 * (sub + 64 * i);
            float av, ax, ay, axx, ayy;
            tanh_jet(v0 + b[j0], dx0, dy0, hx0, hy0, av, ax, ay, axx, ayy);
            s_v[p * HID + j0] = av;
            s_d[p * HID + j0] = make_float2(ax, ay);
            s_h[p * HID + j0] = make_float2(axx, ayy);
            tanh_jet(v1 + b[j0 + 1], dx1, dy1, hx1, hy1, av, ax, ay, axx, ayy);
            s_v[p * HID + j0 + 1] = av;
            s_d[p * HID + j0 + 1] = make_float2(ax, ay);
            s_h[p * HID + j0 + 1] = make_float2(axx, ayy);
        }
        __syncthreads();
    }

    // ---------------- output layer: 512 -> 1 (linear) ----------------
    float pv = 0.0f, pl = 0.0f;   // value partial, laplacian partial
    #pragma unroll
    for (int i = 0; i < 4; i++) {
        int j0 = 2 * (sub + 64 * i);
        #pragma unroll
        for (int h2 = 0; h2 < 2; h2++) {
            int j = j0 + h2;
            float w = W3[j];
            pv = fmaf(s_v[p * HID + j], w, pv);
            float2 hh = s_h[p * HID + j];
            pl = fmaf(hh.x + hh.y, w, pl);
        }
    }
    // reduce over 64 threads (2 warps) of this point
    #pragma unroll
    for (int off = 16; off; off >>= 1) {
        pv += __shfl_down_sync(0xffffffffu, pv, off);
        pl += __shfl_down_sync(0xffffffffu, pl, off);
    }
    float* s_red = s_w;   // reuse W tile space (no one reads s_w anymore)
    if ((tid & 31) == 0) {
        s_red[2 * (tid >> 5)]     = pv;
        s_red[2 * (tid >> 5) + 1] = pl;
    }
    __syncthreads();
    if (sub == 0 && active) {
        int w0i = tid >> 5;   // even warp index of this point
        float uv  = s_red[2 * w0i]     + s_red[2 * (w0i + 1)]     + b3[0];
        float lap = s_red[2 * w0i + 1] + s_red[2 * (w0i + 1) + 1];
        if (gp < n_int) g_lap[gp] = lap;
        else            g_u[gp - n_int] = uv;
    }
}

// ---------------- final deterministic reduction (1 block) ----------------
__global__ void pinn_reduce(const float* __restrict__ xi, float* __restrict__ out,
                            int n_int, int n_bnd)
{
    __shared__ double sh_i[256];
    __shared__ double sh_b[256];
    const int tid = threadIdx.x;
    const float PI = 3.14159265358979f;

    double si = 0.0, sb = 0.0;
    for (int i = tid; i < n_int; i += blockDim.x) {
        float xx = xi[2 * i], yy = xi[2 * i + 1];
        float y2 = yy * yy;
        float sinpx = sinf(PI * xx);
        float spy2, cpy2;
        sincosf(PI * y2, &spy2, &cpy2);
        float f = -PI * PI * (1.0f + 4.0f * y2) * sinpx * spy2
                  + 2.0f * PI * sinpx * cpy2;
        float r = g_lap[i] - f;
        si += (double)r * (double)r;
    }
    for (int i = tid; i < n_bnd; i += blockDim.x) {
        float u = g_u[i];
        sb += (double)u * (double)u;
    }
    sh_i[tid] = si; sh_b[tid] = sb;
    __syncthreads();
    for (int s = 128; s > 0; s >>= 1) {
        if (tid < s) { sh_i[tid] += sh_i[tid + s]; sh_b[tid] += sh_b[tid + s]; }
        __syncthreads();
    }
    if (tid == 0) {
        double il = sh_i[0] / (double)n_int;
        double bl = sh_b[0] / (double)n_bnd;
        out[0] = (float)((double)ALPHA * il + bl);
        out[1] = (float)il;
        out[2] = (float)bl;
    }
}

extern "C" void kernel_launch(void* const* d_in, const int* in_sizes, int n_in,
                              void* d_out, int out_size)
{
    const float* xi = (const float*)d_in[0];
    const float* xb = (const float*)d_in[1];
    const float* W0 = (const float*)d_in[2];
    const float* b0 = (const float*)d_in[3];
    const float* W1 = (const float*)d_in[4];
    const float* b1 = (const float*)d_in[5];
    const float* W2 = (const float*)d_in[6];
    const float* b2 = (const float*)d_in[7];
    const float* W3 = (const float*)d_in[8];
    const float* b3 = (const float*)d_in[9];

    int n_int = in_sizes[0] / 2;
    int n_bnd = in_sizes[1] / 2;
    int n_total = n_int + n_bnd;
    int nblocks = (n_total + G - 1) / G;

    size_t smem_bytes = (size_t)(KT * HID + 5 * G * HID) * sizeof(float);  // 147456
    cudaFuncSetAttribute(pinn_main, cudaFuncAttributeMaxDynamicSharedMemorySize,
                         (int)smem_bytes);

    pinn_main<<<nblocks, T, smem_bytes>>>(xi, xb, W0, b0, W1, b1, W2, b2, W3, b3,
                                          n_int, n_bnd);
    pinn_reduce<<<1, 256>>>(xi, (float*)d_out, n_int, n_bnd);
}

// round 3
// speedup vs baseline: 1.2765x; 1.2765x over previous
#include <cuda_runtime.h>
#include <cstdint>
#include <math.h>

#define HID   512
#define G     8        // points per block
#define T     512      // threads per block
#define KT    32       // K-tile rows staged in shared
#define NTILES (HID / KT)
#define N_INT_MAX 20000
#define N_BND_MAX 800
#define ALPHA 0.01f
#define NB_RED 64
#define RED_T  256

__device__ float  g_lap[N_INT_MAX];
__device__ float  g_u[N_BND_MAX];
__device__ double g_part[2 * NB_RED];

typedef unsigned long long u64;
typedef unsigned int u32;

__device__ __forceinline__ u64 pack2(float lo, float hi) {
    u64 r; asm("mov.b64 %0, {%1,%2};" : "=l"(r) : "f"(lo), "f"(hi)); return r;
}
__device__ __forceinline__ void unpack2(u64 v, float& lo, float& hi) {
    asm("mov.b64 {%0,%1}, %2;" : "=f"(lo), "=f"(hi) : "l"(v));
}
// packed dual fp32 FMA (sm_100+): d = a*b + d, 2x fp32 throughput
__device__ __forceinline__ void fma2(u64& d, u64 a, u64 b) {
    asm("fma.rn.f32x2 %0, %1, %2, %0;" : "+l"(d) : "l"(a), "l"(b));
}
__device__ __forceinline__ void cp16(u32 dst, const float4* src) {
    asm volatile("cp.async.cg.shared.global [%0], [%1], 16;" :: "r"(dst), "l"(src));
}
__device__ __forceinline__ void cp_commit() { asm volatile("cp.async.commit_group;"); }
__device__ __forceinline__ void cp_wait1()  { asm volatile("cp.async.wait_group 1;"); }
__device__ __forceinline__ void cp_wait0()  { asm volatile("cp.async.wait_group 0;"); }

__global__ void __launch_bounds__(T, 1)
pinn_main(const float* __restrict__ xi, const float* __restrict__ xb,
          const float* __restrict__ W0, const float* __restrict__ b0,
          const float* __restrict__ W1, const float* __restrict__ b1,
          const float* __restrict__ W2, const float* __restrict__ b2,
          const float* __restrict__ W3, const float* __restrict__ b3,
          int n_int, int n_bnd)
{
    extern __shared__ float smem[];
    float*  s_w   = smem;                              // 2 * KT * HID floats (128KB)
    float4* s_jet = (float4*)(smem + 2 * KT * HID);    // G * HID float4 (64KB)
    u32 s_w_u32 = (u32)__cvta_generic_to_shared(s_w);

    const int tid = threadIdx.x;
    const int p   = tid >> 6;      // point within block
    const int sub = tid & 63;      // thread within point
    const int gp  = blockIdx.x * G + p;
    const int n_total = n_int + n_bnd;
    const bool active = gp < n_total;

    // prefetch W1 tile 0 into buffer 0 (overlaps with layer-0 compute)
    {
        const float4* src = (const float4*)W1;
        #pragma unroll
        for (int u = 0; u < (KT * HID / 4) / T; u++)
            cp16(s_w_u32 + (tid + u * T) * 16, src + tid + u * T);
        cp_commit();
    }

    float x = 0.0f, y = 0.0f;
    if (active) {
        const float* s = (gp < n_int) ? (xi + 2 * gp) : (xb + 2 * (gp - n_int));
        x = s[0]; y = s[1];
    }

    float4* jet_p = s_jet + p * HID;

    // ---------------- layer 0: (x,y) -> 512, tanh, 4-comp jet (v,gx,gy,L) ----------------
    #pragma unroll
    for (int i = 0; i < 4; i++) {
        #pragma unroll
        for (int h = 0; h < 2; h++) {
            int j = 2 * (sub + 64 * i) + h;
            float wx = W0[j], wy = W0[HID + j];
            float zv = fmaf(x, wx, fmaf(y, wy, b0[j]));
            float t = tanhf(zv);
            float s = 1.0f - t * t;
            float gx = s * wx, gy = s * wy;
            float aL = -2.0f * t * s * (wx * wx + wy * wy);   // z_L = 0 at input
            jet_p[j] = make_float4(t, gx, gy, aL);
        }
    }
    __syncthreads();

    // ---------------- hidden layers: 512 -> 512, tanh ----------------
    #pragma unroll 1
    for (int L = 0; L < 2; L++) {
        const float* Wc = L ? W2 : W1;
        const float* b  = L ? b2 : b1;

        u64 av[4], agx[4], agy[4], aL4[4];
        #pragma unroll
        for (int i = 0; i < 4; i++) { av[i] = 0ull; agx[i] = 0ull; agy[i] = 0ull; aL4[i] = 0ull; }

        #pragma unroll 1
        for (int tile = 0; tile < NTILES; tile++) {
            int gidx = L * NTILES + tile;

            // prefetch next tile into the other buffer (or layer-2 tile 0)
            bool pf = (tile + 1 < NTILES) || (L == 0);
            if (pf) {
                const float* nsrc = (tile + 1 < NTILES) ? (Wc + (tile + 1) * KT * HID) : W2;
                u32 dst = s_w_u32 + ((gidx + 1) & 1) * (KT * HID * 4);
                const float4* src4 = (const float4*)nsrc;
                #pragma unroll
                for (int u = 0; u < (KT * HID / 4) / T; u++)
                    cp16(dst + (tid + u * T) * 16, src4 + tid + u * T);
                cp_commit();
                cp_wait1();   // current tile arrived; next still in flight
            } else {
                cp_wait0();
            }
            __syncthreads();

            const float* wt = s_w + (gidx & 1) * (KT * HID);
            #pragma unroll 4
            for (int k = 0; k < KT; k++) {
                float4 a = jet_p[tile * KT + k];            // broadcast within warp
                u64 AV = pack2(a.x, a.x);
                u64 AX = pack2(a.y, a.y);
                u64 AY = pack2(a.z, a.z);
                u64 AL = pack2(a.w, a.w);
                const u64* wrow = (const u64*)(wt + k * HID) + sub;
                #pragma unroll
                for (int i = 0; i < 4; i++) {
                    u64 wp = wrow[64 * i];
                    fma2(av[i],  AV, wp);
                    fma2(agx[i], AX, wp);
                    fma2(agy[i], AY, wp);
                    fma2(aL4[i], AL, wp);
                }
            }
            __syncthreads();   // all warps done with this buffer before it's refilled
        }

        // epilogue: bias + tanh jet, write back activations
        #pragma unroll
        for (int i = 0; i < 4; i++) {
            float v0, v1, x0, x1, y0, y1, l0, l1;
            unpack2(av[i],  v0, v1);
            unpack2(agx[i], x0, x1);
            unpack2(agy[i], y0, y1);
            unpack2(aL4[i], l0, l1);
            int j0 = 2 * (sub + 64 * i);
            {
                float zv = v0 + b[j0];
                float t = tanhf(zv), s = 1.0f - t * t;
                float gx = s * x0, gy = s * y0;
                float al = fmaf(s, l0, -2.0f * t * s * (x0 * x0 + y0 * y0));
                jet_p[j0] = make_float4(t, gx, gy, al);
            }
            {
                float zv = v1 + b[j0 + 1];
                float t = tanhf(zv), s = 1.0f - t * t;
                float gx = s * x1, gy = s * y1;
                float al = fmaf(s, l1, -2.0f * t * s * (x1 * x1 + y1 * y1));
                jet_p[j0 + 1] = make_float4(t, gx, gy, al);
            }
        }
        __syncthreads();
    }

    // ---------------- output layer: 512 -> 1 (linear) ----------------
    float pv = 0.0f, pl = 0.0f;
    #pragma unroll
    for (int i = 0; i < 4; i++) {
        #pragma unroll
        for (int h = 0; h < 2; h++) {
            int j = 2 * (sub + 64 * i) + h;
            float w = W3[j];
            float4 a = jet_p[j];
            pv = fmaf(a.x, w, pv);
            pl = fmaf(a.w, w, pl);
        }
    }
    #pragma unroll
    for (int off = 16; off; off >>= 1) {
        pv += __shfl_down_sync(0xffffffffu, pv, off);
        pl += __shfl_down_sync(0xffffffffu, pl, off);
    }
    float* s_red = s_w;   // W buffers dead now
    if ((tid & 31) == 0) {
        s_red[2 * (tid >> 5)]     = pv;
        s_red[2 * (tid >> 5) + 1] = pl;
    }
    __syncthreads();
    if (sub == 0 && active) {
        int w0i = tid >> 5;
        float uv  = s_red[2 * w0i]     + s_red[2 * w0i + 2] + b3[0];
        float lap = s_red[2 * w0i + 1] + s_red[2 * w0i + 3];
        if (gp < n_int) g_lap[gp] = lap;
        else            g_u[gp - n_int] = uv;
    }
}

// ---------------- two-stage deterministic reduction ----------------
__global__ void pinn_partial(const float* __restrict__ xi, int n_int, int n_bnd)
{
    __shared__ double sh[2 * RED_T];
    const int tid = threadIdx.x;
    const int stride = NB_RED * RED_T;
    const float PI = 3.14159265358979f;

    double si = 0.0, sb = 0.0;
    for (int i = blockIdx.x * RED_T + tid; i < n_int; i += stride) {
        float xx = xi[2 * i], yy = xi[2 * i + 1];
        float y2 = yy * yy;
        float sp = sinf(PI * xx);
        float s2, c2; sincosf(PI * y2, &s2, &c2);
        float f = -PI * PI * (1.0f + 4.0f * y2) * sp * s2 + 2.0f * PI * sp * c2;
        float r = g_lap[i] - f;
        si += (double)r * r;
    }
    for (int i = blockIdx.x * RED_T + tid; i < n_bnd; i += stride) {
        float u = g_u[i];
        sb += (double)u * u;
    }
    sh[tid] = si; sh[RED_T + tid] = sb;
    __syncthreads();
    for (int s = RED_T / 2; s > 0; s >>= 1) {
        if (tid < s) { sh[tid] += sh[tid + s]; sh[RED_T + tid] += sh[RED_T + tid + s]; }
        __syncthreads();
    }
    if (tid == 0) {
        g_part[blockIdx.x] = sh[0];
        g_part[NB_RED + blockIdx.x] = sh[RED_T];
    }
}

__global__ void pinn_final(float* __restrict__ out, int n_int, int n_bnd)
{
    __shared__ double sh[2 * NB_RED];
    int tid = threadIdx.x;
    if (tid < 2 * NB_RED) sh[tid] = g_part[tid];
    __syncthreads();
    if (tid == 0) {
        double si = 0.0, sb = 0.0;
        for (int i = 0; i < NB_RED; i++) { si += sh[i]; sb += sh[NB_RED + i]; }
        double il = si / (double)n_int;
        double bl = sb / (double)n_bnd;
        out[0] = (float)((double)ALPHA * il + bl);
        out[1] = (float)il;
        out[2] = (float)bl;
    }
}

extern "C" void kernel_launch(void* const* d_in, const int* in_sizes, int n_in,
                              void* d_out, int out_size)
{
    const float* xi = (const float*)d_in[0];
    const float* xb = (const float*)d_in[1];
    const float* W0 = (const float*)d_in[2];
    const float* b0 = (const float*)d_in[3];
    const float* W1 = (const float*)d_in[4];
    const float* b1 = (const float*)d_in[5];
    const float* W2 = (const float*)d_in[6];
    const float* b2 = (const float*)d_in[7];
    const float* W3 = (const float*)d_in[8];
    const float* b3 = (const float*)d_in[9];

    int n_int = in_sizes[0] / 2;
    int n_bnd = in_sizes[1] / 2;
    int n_total = n_int + n_bnd;
    int nblocks = (n_total + G - 1) / G;

    size_t smem_bytes = (size_t)(2 * KT * HID) * sizeof(float)
                      + (size_t)(G * HID) * sizeof(float4);   // 192KB
    cudaFuncSetAttribute(pinn_main, cudaFuncAttributeMaxDynamicSharedMemorySize,
                         (int)smem_bytes);

    pinn_main<<<nblocks, T, smem_bytes>>>(xi, xb, W0, b0, W1, b1, W2, b2, W3, b3,
                                          n_int, n_bnd);
    pinn_partial<<<NB_RED, RED_T>>>(xi, n_int, n_bnd);
    pinn_final<<<1, 128>>>((float*)d_out, n_int, n_bnd);
}

// round 5
// speedup vs baseline: 1.9409x; 1.5204x over previous
#include <cuda_runtime.h>
#include <cuda_bf16.h>
#include <cstdint>
#include <math.h>

typedef unsigned int u32;
typedef unsigned long long u64;

#define HID 512
#define ALPHA 0.01f
#define N_INT_MAX 20000
#define N_BND_MAX 800
#define MT_MAX 656
#define NB_RED 64
#define RED_T 256
#define SMEM_LAYER 200704   // 4096 header + 2 * 98304 tile buffers

// A operand (jets), bf16 hi/lo, layout [stage][mtile][128 rows][512 k]
__device__ __nv_bfloat16 gAh[2][(size_t)MT_MAX * 128 * 512];
__device__ __nv_bfloat16 gAl[2][(size_t)MT_MAX * 128 * 512];
// B operand (W^T), bf16 hi/lo, layout [layer][512 n][512 k]
__device__ __nv_bfloat16 gBh[2][512 * 512];
__device__ __nv_bfloat16 gBl[2][512 * 512];
// per-nhalf partial outputs
__device__ float g_lp[2][N_INT_MAX];
__device__ float g_up[2][N_BND_MAX];
__device__ double g_part[2 * NB_RED];

// ---------------- helpers ----------------
__device__ __forceinline__ void cp16(u32 dst, const void* src) {
    asm volatile("cp.async.cg.shared.global [%0], [%1], 16;" :: "r"(dst), "l"(src));
}
__device__ __forceinline__ void cp_commit() { asm volatile("cp.async.commit_group;"); }
__device__ __forceinline__ void cp_wait1()  { asm volatile("cp.async.wait_group 1;"); }
__device__ __forceinline__ void cp_wait0()  { asm volatile("cp.async.wait_group 0;"); }

__device__ __forceinline__ void ldsm4(u32& r0, u32& r1, u32& r2, u32& r3, u32 addr) {
    asm volatile("ldmatrix.sync.aligned.m8n8.x4.shared.b16 {%0,%1,%2,%3}, [%4];"
        : "=r"(r0), "=r"(r1), "=r"(r2), "=r"(r3) : "r"(addr));
}
__device__ __forceinline__ void mma_bf16(float* c, const u32* a, u32 b0, u32 b1) {
    asm volatile("mma.sync.aligned.m16n8k16.row.col.f32.bf16.bf16.f32 "
        "{%0,%1,%2,%3}, {%4,%5,%6,%7}, {%8,%9}, {%0,%1,%2,%3};"
        : "+f"(c[0]), "+f"(c[1]), "+f"(c[2]), "+f"(c[3])
        : "r"(a[0]), "r"(a[1]), "r"(a[2]), "r"(a[3]), "r"(b0), "r"(b1));
}
__device__ __forceinline__ void split_bf16(float v, __nv_bfloat16& hi, __nv_bfloat16& lo) {
    hi = __float2bfloat16_rn(v);
    lo = __float2bfloat16_rn(v - __bfloat162float(hi));
}

// ---------------- prep: W -> W^T bf16 hi/lo ----------------
__global__ void prep_w(const float* __restrict__ W1, const float* __restrict__ W2) {
    int bid = blockIdx.x;               // 1024 blocks: l*512 + n
    int l = bid >> 9, n = bid & 511;
    const float* W = l ? W2 : W1;
    for (int k = threadIdx.x; k < 512; k += 256) {
        float w = W[(size_t)k * 512 + n];
        __nv_bfloat16 hi, lo; split_bf16(w, hi, lo);
        gBh[l][(size_t)n * 512 + k] = hi;
        gBl[l][(size_t)n * 512 + k] = lo;
    }
}

// ---------------- prep: layer-0 jets -> A0 ----------------
__global__ void __launch_bounds__(256) prep_l0(
    const float* __restrict__ xi, const float* __restrict__ xb,
    const float* __restrict__ W0, const float* __restrict__ b0,
    int n_int, int n_bnd)
{
    __shared__ float s_wx[512], s_wy[512], s_b[512], s_x[32], s_y[32];
    const int tid = threadIdx.x, mt = blockIdx.x;
    for (int i = tid; i < 512; i += 256) {
        s_wx[i] = W0[i]; s_wy[i] = W0[512 + i]; s_b[i] = b0[i];
    }
    if (tid < 32) {
        int gp = mt * 32 + tid;
        float x = 0.f, y = 0.f;
        if (gp < n_int) { x = xi[2 * gp]; y = xi[2 * gp + 1]; }
        else if (gp < n_int + n_bnd) { x = xb[2 * (gp - n_int)]; y = xb[2 * (gp - n_int) + 1]; }
        s_x[tid] = x; s_y[tid] = y;
    }
    __syncthreads();
    __nv_bfloat16* Oh = gAh[0] + (size_t)mt * 65536;
    __nv_bfloat16* Ol = gAl[0] + (size_t)mt * 65536;
    for (int idx = tid; idx < 32 * 512; idx += 256) {
        int p = idx >> 9, n = idx & 511;
        float wx = s_wx[n], wy = s_wy[n];
        float z = fmaf(s_x[p], wx, fmaf(s_y[p], wy, s_b[n]));
        float tt = tanhf(z), sd = 1.f - tt * tt;
        float c[4];
        c[0] = tt; c[1] = sd * wx; c[2] = sd * wy;
        c[3] = -2.f * tt * sd * (wx * wx + wy * wy);
        #pragma unroll
        for (int cc = 0; cc < 4; cc++) {
            size_t off = (size_t)(4 * p + cc) * 512 + n;
            __nv_bfloat16 hi, lo; split_bf16(c[cc], hi, lo);
            Oh[off] = hi; Ol[off] = lo;
        }
    }
}

// ---------------- main GEMM layer (mma.sync bf16, 3-product split) ----------------
// grid (mtiles, 2): blockIdx.y = N-half. 256 threads = 8 warps (4 M x 2 N).
// smem: [0..1KB) bias, [1KB..2KB) W3, [2KB..2.5KB) reduce, [4096..) 2 tile buffers
// buffer: Ah 16KB | Al 16KB | Bh 32KB | Bl 32KB  = 98304 B
template<int FINAL>
__global__ void __launch_bounds__(256, 1) layer_k(
    int sIn, const float* __restrict__ bias, const float* __restrict__ W3,
    int n_int, int n_bnd)
{
    extern __shared__ float smem[];
    u32 sb = (u32)__cvta_generic_to_shared(smem);
    const int tid = threadIdx.x, lane = tid & 31, w = tid >> 5;
    const int warpM = w & 3, warpN = w >> 2;
    const int mt = blockIdx.x, nhalf = blockIdx.y;

    float* s_bias = smem;
    float* s_w3   = smem + 256;
    float* s_red  = smem + 512;       // 128 floats

    for (int i = tid; i < 256; i += 256) {
        s_bias[i] = bias[nhalf * 256 + i];
        if (FINAL) s_w3[i] = W3[nhalf * 256 + i];
    }

    const __nv_bfloat16* Ah = gAh[sIn] + (size_t)mt * 65536;
    const __nv_bfloat16* Al = gAl[sIn] + (size_t)mt * 65536;
    const __nv_bfloat16* Bh = gBh[sIn] + (size_t)nhalf * 256 * 512;
    const __nv_bfloat16* Bl = gBl[sIn] + (size_t)nhalf * 256 * 512;

    auto fill = [&](int kt) {
        u32 base = sb + 4096u + (u32)(kt & 1) * 98304u;
        #pragma unroll
        for (int i = 0; i < 4; i++) {                 // A: 128 rows x 8 chunks
            int q = tid + i * 256, row = q >> 3, ch = q & 7;
            u32 d = base + (u32)row * 128u + (u32)((ch ^ (row & 7)) << 4);
            const __nv_bfloat16* s = Ah + (size_t)row * 512 + kt * 64 + ch * 8;
            cp16(d, s);
            cp16(d + 16384u, Al + (size_t)row * 512 + kt * 64 + ch * 8);
        }
        #pragma unroll
        for (int i = 0; i < 8; i++) {                 // B: 256 rows x 8 chunks
            int q = tid + i * 256, row = q >> 3, ch = q & 7;
            u32 d = base + 32768u + (u32)row * 128u + (u32)((ch ^ (row & 7)) << 4);
            const __nv_bfloat16* s = Bh + (size_t)row * 512 + kt * 64 + ch * 8;
            cp16(d, s);
            cp16(d + 32768u, Bl + (size_t)row * 512 + kt * 64 + ch * 8);
        }
    };

    // ldmatrix lane geometry
    const int rA0 = warpM * 32 + (lane & 7) + (lane & 8);     // + mi*16
    const int cA  = (lane >> 4) & 1;
    const int rB0 = warpN * 128 + (lane & 7) + ((lane & 16) >> 1);  // + ni2*16
    const int cB  = (lane >> 3) & 1;

    float acc[2][16][4];
    #pragma unroll
    for (int mi = 0; mi < 2; mi++)
        #pragma unroll
        for (int ni = 0; ni < 16; ni++)
            #pragma unroll
            for (int r = 0; r < 4; r++) acc[mi][ni][r] = 0.f;

    fill(0); cp_commit();
    fill(1); cp_commit();

    #pragma unroll 1
    for (int kt = 0; kt < 8; kt++) {
        if (kt == 7) cp_wait0(); else cp_wait1();
        __syncthreads();
        u32 tb = sb + 4096u + (u32)(kt & 1) * 98304u;
        #pragma unroll
        for (int ks = 0; ks < 4; ks++) {
            u32 ah[2][4], al[2][4];
            #pragma unroll
            for (int mi = 0; mi < 2; mi++) {
                int row = rA0 + mi * 16;
                u32 ad = tb + (u32)row * 128u + (u32)((((ks * 2 + cA)) ^ (row & 7)) << 4);
                ldsm4(ah[mi][0], ah[mi][1], ah[mi][2], ah[mi][3], ad);
                ldsm4(al[mi][0], al[mi][1], al[mi][2], al[mi][3], ad + 16384u);
            }
            #pragma unroll
            for (int ni2 = 0; ni2 < 8; ni2++) {
                int row = rB0 + ni2 * 16;
                u32 bd = tb + 32768u + (u32)row * 128u + (u32)(((ks * 2 + cB) ^ (row & 7)) << 4);
                u32 bh[4], bl[4];
                ldsm4(bh[0], bh[1], bh[2], bh[3], bd);
                ldsm4(bl[0], bl[1], bl[2], bl[3], bd + 32768u);
                #pragma unroll
                for (int mi = 0; mi < 2; mi++) {
                    float* c0 = acc[mi][ni2 * 2];
                    float* c1 = acc[mi][ni2 * 2 + 1];
                    mma_bf16(c0, ah[mi], bh[0], bh[1]);
                    mma_bf16(c0, al[mi], bh[0], bh[1]);
                    mma_bf16(c0, ah[mi], bl[0], bl[1]);
                    mma_bf16(c1, ah[mi], bh[2], bh[3]);
                    mma_bf16(c1, al[mi], bh[2], bh[3]);
                    mma_bf16(c1, ah[mi], bl[2], bl[3]);
                }
            }
        }
        __syncthreads();
        if (kt + 2 < 8) { fill(kt + 2); cp_commit(); }
    }

    // ---------------- epilogue ----------------
    const int t4 = lane & 3;
    const int gg = lane >> 2;           // 0..7, comp = gg&3
    const int cmy = gg & 3;
    const int baseLane = lane & 0x13;
    float du[4] = {0.f, 0.f, 0.f, 0.f};
    float dl[4] = {0.f, 0.f, 0.f, 0.f};
    __nv_bfloat16* Oh = gAh[sIn ^ 1] + (size_t)mt * 65536;
    __nv_bfloat16* Ol = gAl[sIn ^ 1] + (size_t)mt * 65536;

    #pragma unroll
    for (int mi = 0; mi < 2; mi++) {
        #pragma unroll
        for (int rh = 0; rh < 2; rh++) {
            int R = warpM * 32 + mi * 16 + rh * 8 + gg;
            #pragma unroll
            for (int ni = 0; ni < 16; ni++) {
                float vv[2];
                #pragma unroll
                for (int ch = 0; ch < 2; ch++) {
                    float z = acc[mi][ni][rh * 2 + ch];
                    float zv  = __shfl_sync(0xffffffffu, z, baseLane);
                    float zgx = __shfl_sync(0xffffffffu, z, baseLane | 4);
                    float zgy = __shfl_sync(0xffffffffu, z, baseLane | 8);
                    float zL  = __shfl_sync(0xffffffffu, z, baseLane | 12);
                    int n_loc = warpN * 128 + ni * 8 + 2 * t4 + ch;
                    float tt = tanhf(zv + s_bias[n_loc]);
                    float sd = 1.f - tt * tt;
                    float Lo = fmaf(sd, zL, -2.f * tt * sd * (zgx * zgx + zgy * zgy));
                    if (FINAL) {
                        float w3 = s_w3[n_loc];
                        du[mi * 2 + rh] = fmaf(tt, w3, du[mi * 2 + rh]);
                        dl[mi * 2 + rh] = fmaf(Lo, w3, dl[mi * 2 + rh]);
                    } else {
                        vv[ch] = (cmy == 0) ? tt : (cmy == 1) ? sd * zgx
                               : (cmy == 2) ? sd * zgy : Lo;
                    }
                }
                if (!FINAL) {
                    __nv_bfloat16 h0, l0, h1, l1;
                    split_bf16(vv[0], h0, l0);
                    split_bf16(vv[1], h1, l1);
                    u32 hp = (u32)__bfloat16_as_ushort(h0) | ((u32)__bfloat16_as_ushort(h1) << 16);
                    u32 lp = (u32)__bfloat16_as_ushort(l0) | ((u32)__bfloat16_as_ushort(l1) << 16);
                    size_t eo = (size_t)R * 512 + nhalf * 256 + warpN * 128 + ni * 8 + 2 * t4;
                    *(u32*)(Oh + eo) = hp;
                    *(u32*)(Ol + eo) = lp;
                }
            }
        }
    }

    if (FINAL) {
        #pragma unroll
        for (int s = 0; s < 4; s++) {
            du[s] += __shfl_xor_sync(0xffffffffu, du[s], 1);
            du[s] += __shfl_xor_sync(0xffffffffu, du[s], 2);
            dl[s] += __shfl_xor_sync(0xffffffffu, dl[s], 1);
            dl[s] += __shfl_xor_sync(0xffffffffu, dl[s], 2);
        }
        float* s_u = s_red;            // [warpN*32 + p]
        float* s_l = s_red + 64;
        if (lane == 0 || lane == 16) {
            int ghi = lane >> 4;
            #pragma unroll
            for (int mi = 0; mi < 2; mi++)
                #pragma unroll
                for (int rh = 0; rh < 2; rh++) {
                    int p = warpM * 8 + mi * 4 + rh * 2 + ghi;
                    s_u[warpN * 32 + p] = du[mi * 2 + rh];
                    s_l[warpN * 32 + p] = dl[mi * 2 + rh];
                }
        }
        __syncthreads();
        if (tid < 32) {
            int pt = mt * 32 + tid;
            float us = s_u[tid] + s_u[32 + tid];
            float ls = s_l[tid] + s_l[32 + tid];
            if (pt < n_int) g_lp[nhalf][pt] = ls;
            else if (pt < n_int + n_bnd) g_up[nhalf][pt - n_int] = us;
        }
    }
}

// ---------------- two-stage deterministic reduction ----------------
__global__ void pinn_partial(const float* __restrict__ xi, const float* __restrict__ b3,
                             int n_int, int n_bnd)
{
    __shared__ double sh[2 * RED_T];
    const int tid = threadIdx.x;
    const int stride = NB_RED * RED_T;
    const float PI = 3.14159265358979f;
    float b3v = b3[0];

    double si = 0.0, sb = 0.0;
    for (int i = blockIdx.x * RED_T + tid; i < n_int; i += stride) {
        float xx = xi[2 * i], yy = xi[2 * i + 1];
        float y2 = yy * yy;
        float sp = sinf(PI * xx);
        float s2, c2; sincosf(PI * y2, &s2, &c2);
        float f = -PI * PI * (1.0f + 4.0f * y2) * sp * s2 + 2.0f * PI * sp * c2;
        float r = (g_lp[0][i] + g_lp[1][i]) - f;
        si += (double)r * r;
    }
    for (int i = blockIdx.x * RED_T + tid; i < n_bnd; i += stride) {
        float u = g_up[0][i] + g_up[1][i] + b3v;
        sb += (double)u * u;
    }
    sh[tid] = si; sh[RED_T + tid] = sb;
    __syncthreads();
    for (int s = RED_T / 2; s > 0; s >>= 1) {
        if (tid < s) { sh[tid] += sh[tid + s]; sh[RED_T + tid] += sh[RED_T + tid + s]; }
        __syncthreads();
    }
    if (tid == 0) {
        g_part[blockIdx.x] = sh[0];
        g_part[NB_RED + blockIdx.x] = sh[RED_T];
    }
}

__global__ void pinn_final(float* __restrict__ out, int n_int, int n_bnd)
{
    __shared__ double sh[2 * NB_RED];
    int tid = threadIdx.x;
    if (tid < 2 * NB_RED) sh[tid] = g_part[tid];
    __syncthreads();
    if (tid == 0) {
        double si = 0.0, sb = 0.0;
        for (int i = 0; i < NB_RED; i++) { si += sh[i]; sb += sh[NB_RED + i]; }
        double il = si / (double)n_int;
        double bl = sb / (double)n_bnd;
        out[0] = (float)((double)ALPHA * il + bl);
        out[1] = (float)il;
        out[2] = (float)bl;
    }
}

extern "C" void kernel_launch(void* const* d_in, const int* in_sizes, int n_in,
                              void* d_out, int out_size)
{
    const float* xi = (const float*)d_in[0];
    const float* xb = (const float*)d_in[1];
    const float* W0 = (const float*)d_in[2];
    const float* b0 = (const float*)d_in[3];
    const float* W1 = (const float*)d_in[4];
    const float* b1 = (const float*)d_in[5];
    const float* W2 = (const float*)d_in[6];
    const float* b2 = (const float*)d_in[7];
    const float* W3 = (const float*)d_in[8];
    const float* b3 = (const float*)d_in[9];

    int n_int = in_sizes[0] / 2;
    int n_bnd = in_sizes[1] / 2;
    int n_total = n_int + n_bnd;
    int mtiles = (n_total + 31) / 32;

    static int configured = 0;
    if (!configured) {
        cudaFuncSetAttribute(layer_k<0>, cudaFuncAttributeMaxDynamicSharedMemorySize, SMEM_LAYER);
        cudaFuncSetAttribute(layer_k<1>, cudaFuncAttributeMaxDynamicSharedMemorySize, SMEM_LAYER);
        configured = 1;
    }

    prep_w<<<1024, 256>>>(W1, W2);
    prep_l0<<<mtiles, 256>>>(xi, xb, W0, b0, n_int, n_bnd);
    dim3 grid(mtiles, 2);
    layer_k<0><<<grid, 256, SMEM_LAYER>>>(0, b1, W3, n_int, n_bnd);
    layer_k<1><<<grid, 256, SMEM_LAYER>>>(1, b2, W3, n_int, n_bnd);
    pinn_partial<<<NB_RED, RED_T>>>(xi, b3, n_int, n_bnd);
    pinn_final<<<1, 128>>>((float*)d_out, n_int, n_bnd);
}